// round 16
// baseline (speedup 1.0000x reference)
#include <cuda_runtime.h>
#include <cuda_bf16.h>
#include <math.h>
#include <stdint.h>

#define B 2
#define T 2048
#define C 1024
#define H 16
#define HD 64
#define M_TOT (B*T)   // 4096
#define C2 (C/2)      // packed bf16x2 words per row
#define T2 (T/2)

// ---------------- packed bf16x2 split inputs -------------------------------
__device__ __align__(16) uint32_t g_xh[M_TOT*C2], g_xl[M_TOT*C2];
__device__ __align__(16) uint32_t g_wqh[C*C2], g_wql[C*C2];
__device__ __align__(16) uint32_t g_wkh[C*C2], g_wkl[C*C2];
__device__ __align__(16) uint32_t g_wvh[C*C2], g_wvl[C*C2];
__device__ __align__(16) uint32_t g_woh[C*C2], g_wol[C*C2];
// ---------------- Q/K packed bf16x2; V transposed [b,h,hd,t] packed --------
__device__ __align__(16) uint32_t g_qh[M_TOT*C2], g_ql[M_TOT*C2];
__device__ __align__(16) uint32_t g_kh[M_TOT*C2], g_kl[M_TOT*C2];
__device__ __align__(16) uint32_t g_vth[B*H*HD*T2], g_vtl[B*H*HD*T2];
// ---------------- packed bf16x2 attention output ---------------------------
__device__ __align__(16) uint32_t g_ah[M_TOT*C2], g_al[M_TOT*C2];

// ---------------------------------------------------------------------------
// helpers
// ---------------------------------------------------------------------------
__device__ __forceinline__ void mma_bf16(float* d, const uint32_t* a,
                                         const uint32_t* b) {
    asm volatile(
        "mma.sync.aligned.m16n8k16.row.col.f32.bf16.bf16.f32 "
        "{%0,%1,%2,%3}, {%4,%5,%6,%7}, {%8,%9}, {%0,%1,%2,%3};"
        : "+f"(d[0]), "+f"(d[1]), "+f"(d[2]), "+f"(d[3])
        : "r"(a[0]), "r"(a[1]), "r"(a[2]), "r"(a[3]), "r"(b[0]), "r"(b[1]));
}
__device__ __forceinline__ void ldsm_x4(uint32_t* r, uint32_t a) {
    asm volatile(
        "ldmatrix.sync.aligned.m8n8.x4.shared.b16 {%0,%1,%2,%3}, [%4];"
        : "=r"(r[0]), "=r"(r[1]), "=r"(r[2]), "=r"(r[3]) : "r"(a));
}
__device__ __forceinline__ uint32_t packbf2(float x, float y) {
    __nv_bfloat162 t = __floats2bfloat162_rn(x, y);
    return *reinterpret_cast<uint32_t*>(&t);
}
__device__ __forceinline__ void splitpair(float x, float y,
                                          uint32_t& hw, uint32_t& lw) {
    __nv_bfloat16 hx = __float2bfloat16(x);
    __nv_bfloat16 hy = __float2bfloat16(y);
    float rx = x - __bfloat162float(hx);
    float ry = y - __bfloat162float(hy);
    __nv_bfloat162 hp = {hx, hy};
    hw = *reinterpret_cast<uint32_t*>(&hp);
    lw = packbf2(rx, ry);
}
__device__ __forceinline__ void split1(float v, __nv_bfloat16& h,
                                       __nv_bfloat16& l) {
    h = __float2bfloat16(v);
    l = __float2bfloat16(v - __bfloat162float(h));
}
__device__ __forceinline__ void cp16(uint32_t saddr, const void* gptr) {
    asm volatile("cp.async.cg.shared.global [%0], [%1], 16;\n"
                 :: "r"(saddr), "l"(gptr));
}
#define CP_COMMIT() asm volatile("cp.async.commit_group;\n" ::)
#define CP_WAIT0()  asm volatile("cp.async.wait_group 0;\n" ::)

// ---------------------------------------------------------------------------
// fused split kernel: 5 tensors in one launch (grid.y selects tensor)
// ---------------------------------------------------------------------------
__global__ void split5_kernel(const float4* __restrict__ sx,
                              const float4* __restrict__ sq,
                              const float4* __restrict__ sk,
                              const float4* __restrict__ sv,
                              const float4* __restrict__ so,
                              int nx4, int nw4) {
    const float4* s;
    uint2 *dh, *dl;
    int n4;
    switch (blockIdx.y) {
        case 0:  s = sx; dh = (uint2*)g_xh;  dl = (uint2*)g_xl;  n4 = nx4; break;
        case 1:  s = sq; dh = (uint2*)g_wqh; dl = (uint2*)g_wql; n4 = nw4; break;
        case 2:  s = sk; dh = (uint2*)g_wkh; dl = (uint2*)g_wkl; n4 = nw4; break;
        case 3:  s = sv; dh = (uint2*)g_wvh; dl = (uint2*)g_wvl; n4 = nw4; break;
        default: s = so; dh = (uint2*)g_woh; dl = (uint2*)g_wol; n4 = nw4; break;
    }
    int i = blockIdx.x * blockDim.x + threadIdx.x;
    if (i >= n4) return;
    float4 v = s[i];
    uint2 h, l;
    splitpair(v.x, v.y, h.x, l.x);
    splitpair(v.z, v.w, h.y, l.y);
    dh[i] = h;
    dl[i] = l;
}

// ---------------------------------------------------------------------------
// Fused QKV GEMM, bf16 3-term, cp.async double-buffered, LDSM fragments,
// term-major MMA ordering (16 independent MMAs between dependent pairs).
// ---------------------------------------------------------------------------
#define BM 128
#define BN 128
#define KW 16
#define KP 20
#define GSTAGE 10240
#define NKIT (C2/KW)

// term-major MMA block shared by qkv/wo inner loops
#define GEMM_MMA_BLOCK()                                                      \
    do {                                                                      \
        _Pragma("unroll")                                                     \
        for (int p = 0; p < 2; p++)                                           \
            _Pragma("unroll")                                                 \
            for (int hb = 0; hb < 2; hb++)                                    \
                _Pragma("unroll")                                             \
                for (int mt = 0; mt < 4; mt++)                                \
                    mma_bf16(acc[mt][2 * p + hb], ah[mt], &bhf[p][2 * hb]);   \
        _Pragma("unroll")                                                     \
        for (int p = 0; p < 2; p++)                                           \
            _Pragma("unroll")                                                 \
            for (int hb = 0; hb < 2; hb++)                                    \
                _Pragma("unroll")                                             \
                for (int mt = 0; mt < 4; mt++)                                \
                    mma_bf16(acc[mt][2 * p + hb], al[mt], &bhf[p][2 * hb]);   \
        _Pragma("unroll")                                                     \
        for (int p = 0; p < 2; p++)                                           \
            _Pragma("unroll")                                                 \
            for (int hb = 0; hb < 2; hb++)                                    \
                _Pragma("unroll")                                             \
                for (int mt = 0; mt < 4; mt++)                                \
                    mma_bf16(acc[mt][2 * p + hb], ah[mt], &blf[p][2 * hb]);   \
    } while (0)

__global__ void __launch_bounds__(256, 2) qkv_gemm(const float* __restrict__ cosp,
                                                   const float* __restrict__ sinp) {
    extern __shared__ uint32_t sm[];
    const int tid = threadIdx.x, lane = tid & 31, warp = tid >> 5;
    const int warpM = warp >> 2, warpN = warp & 3;
    const int grp = lane >> 2, tg = lane & 3;
    const int m0 = blockIdx.y * BM;
    const int nsel = blockIdx.x >> 3;
    const int n0c = (blockIdx.x & 7) * BN;

    const uint32_t* WH = (nsel == 0) ? g_wqh : (nsel == 1) ? g_wkh : g_wvh;
    const uint32_t* WL = (nsel == 0) ? g_wql : (nsel == 1) ? g_wkl : g_wvl;

    const int lrow = tid >> 2;
    const int lwq  = (tid & 3) << 2;
    const uint32_t sb = (uint32_t)__cvta_generic_to_shared(sm);
    const int lm = lane >> 3;
    const uint32_t aOffW = (uint32_t)((warpM * 64 + (lm & 1) * 8 + (lane & 7)) * KP
                                      + (lm >> 1) * 4);
    const uint32_t bOffW = (uint32_t)((warpN * 32 + (lm >> 1) * 8 + (lane & 7)) * KP
                                      + (lm & 1) * 4);

    float acc[4][4][4];
    #pragma unroll
    for (int mt = 0; mt < 4; mt++)
        #pragma unroll
        for (int nt = 0; nt < 4; nt++)
            #pragma unroll
            for (int i = 0; i < 4; i++) acc[mt][nt][i] = 0.f;

    #define QKV_ISSUE(stg, k0w) do {                                          \
        uint32_t base_ = sb + (stg) * (GSTAGE * 4);                           \
        size_t rA0_ = (size_t)(m0 + lrow) * C2 + (k0w) + lwq;                 \
        size_t rA1_ = (size_t)(m0 + lrow + 64) * C2 + (k0w) + lwq;            \
        size_t rB0_ = (size_t)(n0c + lrow) * C2 + (k0w) + lwq;                \
        size_t rB1_ = (size_t)(n0c + lrow + 64) * C2 + (k0w) + lwq;           \
        uint32_t dA0_ = base_ + (lrow * KP + lwq) * 4;                        \
        uint32_t dA1_ = base_ + ((lrow + 64) * KP + lwq) * 4;                 \
        cp16(dA0_, &g_xh[rA0_]);  cp16(dA1_, &g_xh[rA1_]);                    \
        cp16(dA0_ + 2560 * 4, &g_xl[rA0_]);                                   \
        cp16(dA1_ + 2560 * 4, &g_xl[rA1_]);                                   \
        uint32_t dB0_ = base_ + (5120 + lrow * KP + lwq) * 4;                 \
        uint32_t dB1_ = base_ + (5120 + (lrow + 64) * KP + lwq) * 4;          \
        cp16(dB0_, &WH[rB0_]);  cp16(dB1_, &WH[rB1_]);                        \
        cp16(dB0_ + 2560 * 4, &WL[rB0_]);                                     \
        cp16(dB1_ + 2560 * 4, &WL[rB1_]);                                     \
        CP_COMMIT();                                                          \
    } while (0)

    QKV_ISSUE(0, 0);

    for (int it = 0; it < NKIT; it++) {
        CP_WAIT0();
        __syncthreads();
        if (it + 1 < NKIT) QKV_ISSUE((it + 1) & 1, (it + 1) * KW);

        const uint32_t stg = sb + (it & 1) * (GSTAGE * 4);

        #pragma unroll
        for (int s8 = 0; s8 < KW; s8 += 8) {
            uint32_t ah[4][4], al[4][4];
            #pragma unroll
            for (int mt = 0; mt < 4; mt++) {
                ldsm_x4(ah[mt], stg + (mt * 16 * KP + s8 + aOffW) * 4);
                ldsm_x4(al[mt], stg + (2560 + mt * 16 * KP + s8 + aOffW) * 4);
            }
            uint32_t bhf[2][4], blf[2][4];
            #pragma unroll
            for (int p = 0; p < 2; p++) {
                ldsm_x4(bhf[p], stg + (5120 + p * 16 * KP + s8 + bOffW) * 4);
                ldsm_x4(blf[p], stg + (7680 + p * 16 * KP + s8 + bOffW) * 4);
            }
            GEMM_MMA_BLOCK();
        }
    }

    // epilogue
    uint32_t* QKH = (nsel == 0) ? g_qh : g_kh;
    uint32_t* QKL = (nsel == 0) ? g_ql : g_kl;
    __nv_bfloat16* VTH = (__nv_bfloat16*)g_vth;
    __nv_bfloat16* VTL = (__nv_bfloat16*)g_vtl;
    #pragma unroll
    for (int mt = 0; mt < 4; mt++) {
        int rowA = m0 + warpM * 64 + mt * 16 + grp;
        int rowB = rowA + 8;
        #pragma unroll
        for (int nt = 0; nt < 4; nt++) {
            int c = n0c + warpN * 32 + nt * 8 + 2 * tg;
            float a0 = acc[mt][nt][0], a1 = acc[mt][nt][1];
            float a2 = acc[mt][nt][2], a3 = acc[mt][nt][3];
            if (nsel < 2) {
                int d = (c & 63) >> 1;
                int t0 = rowA & (T - 1), t1 = rowB & (T - 1);
                float c0 = cosp[t0 * 32 + d], s0 = sinp[t0 * 32 + d];
                float c1 = cosp[t1 * 32 + d], s1 = sinp[t1 * 32 + d];
                float o0 = a0 * c0 - a1 * s0, o1 = a0 * s0 + a1 * c0;
                float o2 = a2 * c1 - a3 * s1, o3 = a2 * s1 + a3 * c1;
                uint32_t hw, lw;
                splitpair(o0, o1, hw, lw);
                QKH[(size_t)rowA * C2 + (c >> 1)] = hw;
                QKL[(size_t)rowA * C2 + (c >> 1)] = lw;
                splitpair(o2, o3, hw, lw);
                QKH[(size_t)rowB * C2 + (c >> 1)] = hw;
                QKL[(size_t)rowB * C2 + (c >> 1)] = lw;
            } else {
                int bb = rowA >> 11;
                int hh = c >> 6, hd = c & 63;
                size_t base = ((size_t)(bb * H + hh) * HD + hd) * T;
                int tA = rowA & (T - 1), tB = rowB & (T - 1);
                float vals[4] = {a0, a1, a2, a3};
                size_t idxs[4] = {base + tA, base + T + tA,
                                  base + tB, base + T + tB};
                #pragma unroll
                for (int j = 0; j < 4; j++) {
                    __nv_bfloat16 hv, lv;
                    split1(vals[j], hv, lv);
                    VTH[idxs[j]] = hv;
                    VTL[idxs[j]] = lv;
                }
            }
        }
    }
}

// ---------------------------------------------------------------------------
// Output GEMM: out = att @ Wo^T, LDSM + term-major MMAs.
// ---------------------------------------------------------------------------
__global__ void __launch_bounds__(256, 2) wo_gemm(float* __restrict__ out) {
    extern __shared__ uint32_t sm[];
    const int tid = threadIdx.x, lane = tid & 31, warp = tid >> 5;
    const int warpM = warp >> 2, warpN = warp & 3;
    const int grp = lane >> 2, tg = lane & 3;
    const int m0 = blockIdx.y * BM;
    const int n0 = blockIdx.x * BN;

    const int lrow = tid >> 2;
    const int lwq  = (tid & 3) << 2;
    const uint32_t sb = (uint32_t)__cvta_generic_to_shared(sm);
    const int lm = lane >> 3;
    const uint32_t aOffW = (uint32_t)((warpM * 64 + (lm & 1) * 8 + (lane & 7)) * KP
                                      + (lm >> 1) * 4);
    const uint32_t bOffW = (uint32_t)((warpN * 32 + (lm >> 1) * 8 + (lane & 7)) * KP
                                      + (lm & 1) * 4);

    float acc[4][4][4];
    #pragma unroll
    for (int mt = 0; mt < 4; mt++)
        #pragma unroll
        for (int nt = 0; nt < 4; nt++)
            #pragma unroll
            for (int i = 0; i < 4; i++) acc[mt][nt][i] = 0.f;

    #define WO_ISSUE(stg, k0w) do {                                           \
        uint32_t base_ = sb + (stg) * (GSTAGE * 4);                           \
        size_t rA0_ = (size_t)(m0 + lrow) * C2 + (k0w) + lwq;                 \
        size_t rA1_ = (size_t)(m0 + lrow + 64) * C2 + (k0w) + lwq;            \
        size_t rB0_ = (size_t)(n0 + lrow) * C2 + (k0w) + lwq;                 \
        size_t rB1_ = (size_t)(n0 + lrow + 64) * C2 + (k0w) + lwq;            \
        uint32_t dA0_ = base_ + (lrow * KP + lwq) * 4;                        \
        uint32_t dA1_ = base_ + ((lrow + 64) * KP + lwq) * 4;                 \
        cp16(dA0_, &g_ah[rA0_]);  cp16(dA1_, &g_ah[rA1_]);                    \
        cp16(dA0_ + 2560 * 4, &g_al[rA0_]);                                   \
        cp16(dA1_ + 2560 * 4, &g_al[rA1_]);                                   \
        uint32_t dB0_ = base_ + (5120 + lrow * KP + lwq) * 4;                 \
        uint32_t dB1_ = base_ + (5120 + (lrow + 64) * KP + lwq) * 4;          \
        cp16(dB0_, &g_woh[rB0_]);  cp16(dB1_, &g_woh[rB1_]);                  \
        cp16(dB0_ + 2560 * 4, &g_wol[rB0_]);                                  \
        cp16(dB1_ + 2560 * 4, &g_wol[rB1_]);                                  \
        CP_COMMIT();                                                          \
    } while (0)

    WO_ISSUE(0, 0);

    for (int it = 0; it < NKIT; it++) {
        CP_WAIT0();
        __syncthreads();
        if (it + 1 < NKIT) WO_ISSUE((it + 1) & 1, (it + 1) * KW);

        const uint32_t stg = sb + (it & 1) * (GSTAGE * 4);

        #pragma unroll
        for (int s8 = 0; s8 < KW; s8 += 8) {
            uint32_t ah[4][4], al[4][4];
            #pragma unroll
            for (int mt = 0; mt < 4; mt++) {
                ldsm_x4(ah[mt], stg + (mt * 16 * KP + s8 + aOffW) * 4);
                ldsm_x4(al[mt], stg + (2560 + mt * 16 * KP + s8 + aOffW) * 4);
            }
            uint32_t bhf[2][4], blf[2][4];
            #pragma unroll
            for (int p = 0; p < 2; p++) {
                ldsm_x4(bhf[p], stg + (5120 + p * 16 * KP + s8 + bOffW) * 4);
                ldsm_x4(blf[p], stg + (7680 + p * 16 * KP + s8 + bOffW) * 4);
            }
            GEMM_MMA_BLOCK();
        }
    }

    #pragma unroll
    for (int mt = 0; mt < 4; mt++) {
        int rowA = m0 + warpM * 64 + mt * 16 + grp;
        #pragma unroll
        for (int nt = 0; nt < 4; nt++) {
            int c = n0 + warpN * 32 + nt * 8 + 2 * tg;
            *(float2*)&out[(size_t)rowA * C + c] =
                make_float2(acc[mt][nt][0], acc[mt][nt][1]);
            *(float2*)&out[(size_t)(rowA + 8) * C + c] =
                make_float2(acc[mt][nt][2], acc[mt][nt][3]);
        }
    }
}

// ---------------------------------------------------------------------------
// Causal flash attention: full bf16 3-term, KB=64 tiles, LDSM fragments,
// occupancy 3, term-major MMA ordering.
// ---------------------------------------------------------------------------
#define QB 64
#define KB 64
#define KSW 36
#define VSW 36
#define AST_KL 2304
#define AST_VH 4608
#define AST_VL 6912
#define ASTAGE 9216

__global__ void __launch_bounds__(128, 3) attn_kernel() {
    extern __shared__ uint32_t sm[];

    const int tid  = threadIdx.x;
    const int lane = tid & 31;
    const int warp = tid >> 5;
    const int grp  = lane >> 2;
    const int tg   = lane & 3;
    const int bh   = blockIdx.y;
    const int b    = bh >> 4, h = bh & 15;
    const int qx   = gridDim.x - 1 - (int)blockIdx.x;   // heavy blocks first
    const int q0   = qx * QB;
    const int r0   = q0 + warp * 16;
    const uint32_t sb = (uint32_t)__cvta_generic_to_shared(sm);
    const size_t vbase = ((size_t)(b * H + h)) * HD * T2;
    const int lm = lane >> 3;
    const uint32_t kOffW = (uint32_t)(((lm >> 1) * 8 + (lane & 7)) * KSW
                                      + (lm & 1) * 4);
    const uint32_t vOffW = (uint32_t)(((lm >> 1) * 8 + (lane & 7)) * VSW
                                      + (lm & 1) * 4);

    uint32_t qfh[4][4], qfl[4][4];
    {
        const uint32_t* QHa = g_qh + ((size_t)(b * T + r0)) * C2 + h * 32;
        const uint32_t* QLa = g_ql + ((size_t)(b * T + r0)) * C2 + h * 32;
        #pragma unroll
        for (int ks = 0; ks < 4; ks++) {
            qfh[ks][0] = QHa[(size_t)grp * C2 + ks * 8 + tg];
            qfh[ks][1] = QHa[(size_t)(grp + 8) * C2 + ks * 8 + tg];
            qfh[ks][2] = QHa[(size_t)grp * C2 + ks * 8 + tg + 4];
            qfh[ks][3] = QHa[(size_t)(grp + 8) * C2 + ks * 8 + tg + 4];
            qfl[ks][0] = QLa[(size_t)grp * C2 + ks * 8 + tg];
            qfl[ks][1] = QLa[(size_t)(grp + 8) * C2 + ks * 8 + tg];
            qfl[ks][2] = QLa[(size_t)grp * C2 + ks * 8 + tg + 4];
            qfl[ks][3] = QLa[(size_t)(grp + 8) * C2 + ks * 8 + tg + 4];
        }
    }

    float out[8][4];
    #pragma unroll
    for (int i = 0; i < 8; i++)
        #pragma unroll
        for (int j = 0; j < 4; j++) out[i][j] = 0.f;
    float m0v = -1e30f, m1v = -1e30f, l0 = 0.f, l1 = 0.f;

    const int nIter = qx + 1;

    #define ATT_ISSUE(stg, k0) do {                                           \
        uint32_t base_ = sb + (stg) * (ASTAGE * 4);                           \
        _Pragma("unroll")                                                     \
        for (int i_ = 0; i_ < 4; i_++) {                                      \
            int idk_ = tid + i_ * 128;                                        \
            int krow_ = idk_ >> 3, kwq_ = (idk_ & 7) << 2;                    \
            size_t koff_ = ((size_t)(b * T + (k0) + krow_)) * C2 + h * 32 + kwq_; \
            cp16(base_ + (krow_ * KSW + kwq_) * 4, &g_kh[koff_]);             \
            cp16(base_ + (AST_KL + krow_ * KSW + kwq_) * 4, &g_kl[koff_]);    \
            size_t voff_ = vbase + (size_t)krow_ * T2 + ((k0) >> 1) + kwq_;   \
            cp16(base_ + (AST_VH + krow_ * VSW + kwq_) * 4, &g_vth[voff_]);   \
            cp16(base_ + (AST_VL + krow_ * VSW + kwq_) * 4, &g_vtl[voff_]);   \
        }                                                                     \
        CP_COMMIT();                                                          \
    } while (0)

    ATT_ISSUE(0, 0);

    for (int t = 0; t < nIter; t++) {
        const int k0 = t * KB;
        CP_WAIT0();
        __syncthreads();
        if (t + 1 < nIter) ATT_ISSUE((t + 1) & 1, (t + 1) * KB);

        if (k0 > r0 + 15) continue;

        const uint32_t stg = sb + (t & 1) * (ASTAGE * 4);

        // ---- S = Q K^T (16 x 64), bf16 3-term, LDSM, term-major ----
        float s[8][4];
        #pragma unroll
        for (int nt = 0; nt < 8; nt++)
            #pragma unroll
            for (int j = 0; j < 4; j++) s[nt][j] = 0.f;

        #pragma unroll
        for (int ks = 0; ks < 4; ks++) {
            uint32_t kh4[4][4], kl4[4][4];
            #pragma unroll
            for (int p = 0; p < 4; p++) {
                ldsm_x4(kh4[p], stg + (p * 16 * KSW + ks * 8 + kOffW) * 4);
                ldsm_x4(kl4[p], stg + (AST_KL * 4) + (p * 16 * KSW + ks * 8 + kOffW) * 4);
            }
            #pragma unroll
            for (int p = 0; p < 4; p++)
                #pragma unroll
                for (int hb = 0; hb < 2; hb++)
                    mma_bf16(s[2 * p + hb], qfh[ks], &kh4[p][2 * hb]);
            #pragma unroll
            for (int p = 0; p < 4; p++)
                #pragma unroll
                for (int hb = 0; hb < 2; hb++)
                    mma_bf16(s[2 * p + hb], qfl[ks], &kh4[p][2 * hb]);
            #pragma unroll
            for (int p = 0; p < 4; p++)
                #pragma unroll
                for (int hb = 0; hb < 2; hb++)
                    mma_bf16(s[2 * p + hb], qfh[ks], &kl4[p][2 * hb]);
        }

        // ---- scale + causal mask ----
        const int row0 = r0 + grp, row1 = r0 + grp + 8;
        if (k0 + KB - 1 <= r0) {
            #pragma unroll
            for (int nt = 0; nt < 8; nt++)
                #pragma unroll
                for (int j = 0; j < 4; j++) s[nt][j] *= 0.125f;
        } else {
            #pragma unroll
            for (int nt = 0; nt < 8; nt++) {
                int col = k0 + nt * 8 + 2 * tg;
                s[nt][0] = (col     <= row0) ? s[nt][0] * 0.125f : -1e30f;
                s[nt][1] = (col + 1 <= row0) ? s[nt][1] * 0.125f : -1e30f;
                s[nt][2] = (col     <= row1) ? s[nt][2] * 0.125f : -1e30f;
                s[nt][3] = (col + 1 <= row1) ? s[nt][3] * 0.125f : -1e30f;
            }
        }

        // ---- online softmax ----
        float mx0 = s[0][0], mx1 = s[0][2];
        #pragma unroll
        for (int nt = 0; nt < 8; nt++) {
            mx0 = fmaxf(mx0, fmaxf(s[nt][0], s[nt][1]));
            mx1 = fmaxf(mx1, fmaxf(s[nt][2], s[nt][3]));
        }
        mx0 = fmaxf(mx0, __shfl_xor_sync(0xffffffffu, mx0, 1));
        mx0 = fmaxf(mx0, __shfl_xor_sync(0xffffffffu, mx0, 2));
        mx1 = fmaxf(mx1, __shfl_xor_sync(0xffffffffu, mx1, 1));
        mx1 = fmaxf(mx1, __shfl_xor_sync(0xffffffffu, mx1, 2));
        float nm0 = fmaxf(m0v, mx0), nm1 = fmaxf(m1v, mx1);
        float c0 = __expf(m0v - nm0), c1 = __expf(m1v - nm1);

        float sum0 = 0.f, sum1 = 0.f;
        #pragma unroll
        for (int nt = 0; nt < 8; nt++) {
            s[nt][0] = __expf(s[nt][0] - nm0);
            s[nt][1] = __expf(s[nt][1] - nm0);
            s[nt][2] = __expf(s[nt][2] - nm1);
            s[nt][3] = __expf(s[nt][3] - nm1);
            sum0 += s[nt][0] + s[nt][1];
            sum1 += s[nt][2] + s[nt][3];
        }
        sum0 += __shfl_xor_sync(0xffffffffu, sum0, 1);
        sum0 += __shfl_xor_sync(0xffffffffu, sum0, 2);
        sum1 += __shfl_xor_sync(0xffffffffu, sum1, 1);
        sum1 += __shfl_xor_sync(0xffffffffu, sum1, 2);
        l0 = l0 * c0 + sum0;
        l1 = l1 * c1 + sum1;
        m0v = nm0; m1v = nm1;

        #pragma unroll
        for (int i = 0; i < 8; i++) {
            out[i][0] *= c0; out[i][1] *= c0;
            out[i][2] *= c1; out[i][3] *= c1;
        }

        // ---- PV: bf16 3-term, LDSM V fragments, term-major ----
        #pragma unroll
        for (int ks = 0; ks < 4; ks++) {
            uint32_t ph[4], pl[4];
            splitpair(s[2 * ks][0],     s[2 * ks][1],     ph[0], pl[0]);
            splitpair(s[2 * ks][2],     s[2 * ks][3],     ph[1], pl[1]);
            splitpair(s[2 * ks + 1][0], s[2 * ks + 1][1], ph[2], pl[2]);
            splitpair(s[2 * ks + 1][2], s[2 * ks + 1][3], ph[3], pl[3]);
            uint32_t vh4[4][4], vl4[4][4];
            #pragma unroll
            for (int p = 0; p < 4; p++) {
                ldsm_x4(vh4[p], stg + (AST_VH * 4) + (p * 16 * VSW + ks * 8 + vOffW) * 4);
                ldsm_x4(vl4[p], stg + (AST_VL * 4) + (p * 16 * VSW + ks * 8 + vOffW) * 4);
            }
            #pragma unroll
            for (int p = 0; p < 4; p++)
                #pragma unroll
                for (int hb = 0; hb < 2; hb++)
                    mma_bf16(out[2 * p + hb], ph, &vh4[p][2 * hb]);
            #pragma unroll
            for (int p = 0; p < 4; p++)
                #pragma unroll
                for (int hb = 0; hb < 2; hb++)
                    mma_bf16(out[2 * p + hb], pl, &vh4[p][2 * hb]);
            #pragma unroll
            for (int p = 0; p < 4; p++)
                #pragma unroll
                for (int hb = 0; hb < 2; hb++)
                    mma_bf16(out[2 * p + hb], ph, &vl4[p][2 * hb]);
        }
    }

    // normalize + bf16 splitpair + packed store
    float inv0 = 1.f / l0, inv1 = 1.f / l1;
    size_t rA = ((size_t)(b * T + r0 + grp)) * C2 + h * 32;
    size_t rB = ((size_t)(b * T + r0 + grp + 8)) * C2 + h * 32;
    #pragma unroll
    for (int ntv = 0; ntv < 8; ntv++) {
        int cw = ntv * 4 + tg;
        uint32_t hw, lw;
        splitpair(out[ntv][0] * inv0, out[ntv][1] * inv0, hw, lw);
        g_ah[rA + cw] = hw;
        g_al[rA + cw] = lw;
        splitpair(out[ntv][2] * inv1, out[ntv][3] * inv1, hw, lw);
        g_ah[rB + cw] = hw;
        g_al[rB + cw] = lw;
    }
}

// ---------------------------------------------------------------------------
extern "C" void kernel_launch(void* const* d_in, const int* in_sizes, int n_in,
                              void* d_out, int out_size) {
    const float* x    = (const float*)d_in[0];
    const float* Wq   = (const float*)d_in[1];
    const float* Wk   = (const float*)d_in[2];
    const float* Wv   = (const float*)d_in[3];
    const float* Wo   = (const float*)d_in[4];
    const float* cosp = (const float*)d_in[5];
    const float* sinp = (const float*)d_in[6];
    float* out = (float*)d_out;

    static bool attr_done = false;
    if (!attr_done) {
        cudaFuncSetAttribute(qkv_gemm,
            cudaFuncAttributeMaxDynamicSharedMemorySize, 2 * GSTAGE * 4);
        cudaFuncSetAttribute(wo_gemm,
            cudaFuncAttributeMaxDynamicSharedMemorySize, 2 * GSTAGE * 4);
        cudaFuncSetAttribute(attn_kernel,
            cudaFuncAttributeMaxDynamicSharedMemorySize, 2 * ASTAGE * 4);
        attr_done = true;
    }

    int nx4 = M_TOT * C / 4;
    int nw4 = C * C / 4;
    split5_kernel<<<dim3(nx4 / 256, 5), 256>>>(
        (const float4*)x, (const float4*)Wq, (const float4*)Wk,
        (const float4*)Wv, (const float4*)Wo, nx4, nw4);

    qkv_gemm<<<dim3(24, M_TOT / BM), 256, 2 * GSTAGE * 4>>>(cosp, sinp);

    attn_kernel<<<dim3(T / QB, B * H), 128, 2 * ASTAGE * 4>>>();

    wo_gemm<<<dim3(C / BN, M_TOT / BM), 256, 2 * GSTAGE * 4>>>(out);
}

// round 17
// speedup vs baseline: 1.2287x; 1.2287x over previous
#include <cuda_runtime.h>
#include <cuda_bf16.h>
#include <cuda_fp16.h>
#include <math.h>
#include <stdint.h>

#define B 2
#define T 2048
#define C 1024
#define H 16
#define HD 64
#define M_TOT (B*T)   // 4096
#define C2 (C/2)      // packed 16-bit-pair words per row
#define T2 (T/2)

// ---------------- GEMM operands: fp16 ---------------------------------------
// x: fp16 2-term split; W: single fp16
__device__ __align__(16) uint32_t g_xh[M_TOT*C2], g_xl[M_TOT*C2];
__device__ __align__(16) uint32_t g_wq[C*C2], g_wk[C*C2];
__device__ __align__(16) uint32_t g_wv[C*C2], g_wo[C*C2];
// ---------------- attention operands: bf16 (validated path) -----------------
__device__ __align__(16) uint32_t g_qh[M_TOT*C2], g_ql[M_TOT*C2];
__device__ __align__(16) uint32_t g_kh[M_TOT*C2], g_kl[M_TOT*C2];
__device__ __align__(16) uint32_t g_vth[B*H*HD*T2], g_vtl[B*H*HD*T2];
// ---------------- attention output: fp16 2-term (wo_gemm A operand) ---------
__device__ __align__(16) uint32_t g_ah[M_TOT*C2], g_al[M_TOT*C2];

// ---------------------------------------------------------------------------
// helpers
// ---------------------------------------------------------------------------
__device__ __forceinline__ void mma_bf16(float* d, const uint32_t* a,
                                         const uint32_t* b) {
    asm volatile(
        "mma.sync.aligned.m16n8k16.row.col.f32.bf16.bf16.f32 "
        "{%0,%1,%2,%3}, {%4,%5,%6,%7}, {%8,%9}, {%0,%1,%2,%3};"
        : "+f"(d[0]), "+f"(d[1]), "+f"(d[2]), "+f"(d[3])
        : "r"(a[0]), "r"(a[1]), "r"(a[2]), "r"(a[3]), "r"(b[0]), "r"(b[1]));
}
__device__ __forceinline__ void mma_fp16(float* d, const uint32_t* a,
                                         const uint32_t* b) {
    asm volatile(
        "mma.sync.aligned.m16n8k16.row.col.f32.f16.f16.f32 "
        "{%0,%1,%2,%3}, {%4,%5,%6,%7}, {%8,%9}, {%0,%1,%2,%3};"
        : "+f"(d[0]), "+f"(d[1]), "+f"(d[2]), "+f"(d[3])
        : "r"(a[0]), "r"(a[1]), "r"(a[2]), "r"(a[3]), "r"(b[0]), "r"(b[1]));
}
__device__ __forceinline__ void ldsm_x4(uint32_t* r, uint32_t a) {
    asm volatile(
        "ldmatrix.sync.aligned.m8n8.x4.shared.b16 {%0,%1,%2,%3}, [%4];"
        : "=r"(r[0]), "=r"(r[1]), "=r"(r[2]), "=r"(r[3]) : "r"(a));
}
__device__ __forceinline__ uint32_t packbf2(float x, float y) {
    __nv_bfloat162 t = __floats2bfloat162_rn(x, y);
    return *reinterpret_cast<uint32_t*>(&t);
}
__device__ __forceinline__ void splitpair(float x, float y,
                                          uint32_t& hw, uint32_t& lw) {
    __nv_bfloat16 hx = __float2bfloat16(x);
    __nv_bfloat16 hy = __float2bfloat16(y);
    float rx = x - __bfloat162float(hx);
    float ry = y - __bfloat162float(hy);
    __nv_bfloat162 hp = {hx, hy};
    hw = *reinterpret_cast<uint32_t*>(&hp);
    lw = packbf2(rx, ry);
}
__device__ __forceinline__ void split1(float v, __nv_bfloat16& h,
                                       __nv_bfloat16& l) {
    h = __float2bfloat16(v);
    l = __float2bfloat16(v - __bfloat162float(h));
}
__device__ __forceinline__ uint32_t packh2(float x, float y) {
    __half2 t = __floats2half2_rn(x, y);
    return *reinterpret_cast<uint32_t*>(&t);
}
__device__ __forceinline__ void splitpair_h(float x, float y,
                                            uint32_t& hw, uint32_t& lw) {
    __half hx = __float2half_rn(x);
    __half hy = __float2half_rn(y);
    float rx = x - __half2float(hx);
    float ry = y - __half2float(hy);
    __half2 hp = {hx, hy};
    hw = *reinterpret_cast<uint32_t*>(&hp);
    lw = packh2(rx, ry);
}
__device__ __forceinline__ void cp16(uint32_t saddr, const void* gptr) {
    asm volatile("cp.async.cg.shared.global [%0], [%1], 16;\n"
                 :: "r"(saddr), "l"(gptr));
}
#define CP_COMMIT() asm volatile("cp.async.commit_group;\n" ::)
#define CP_WAIT0()  asm volatile("cp.async.wait_group 0;\n" ::)

// ---------------------------------------------------------------------------
// fused split kernel: x -> fp16 hi/lo; weights -> single fp16 pack
// ---------------------------------------------------------------------------
__global__ void split5_kernel(const float4* __restrict__ sx,
                              const float4* __restrict__ sq,
                              const float4* __restrict__ sk,
                              const float4* __restrict__ sv,
                              const float4* __restrict__ so,
                              int nx4, int nw4) {
    int i = blockIdx.x * blockDim.x + threadIdx.x;
    if (blockIdx.y == 0) {
        if (i >= nx4) return;
        float4 v = sx[i];
        uint2 h, l;
        splitpair_h(v.x, v.y, h.x, l.x);
        splitpair_h(v.z, v.w, h.y, l.y);
        ((uint2*)g_xh)[i] = h;
        ((uint2*)g_xl)[i] = l;
    } else {
        if (i >= nw4) return;
        const float4* s;
        uint2* d;
        switch (blockIdx.y) {
            case 1:  s = sq; d = (uint2*)g_wq; break;
            case 2:  s = sk; d = (uint2*)g_wk; break;
            case 3:  s = sv; d = (uint2*)g_wv; break;
            default: s = so; d = (uint2*)g_wo; break;
        }
        float4 v = s[i];
        d[i] = make_uint2(packh2(v.x, v.y), packh2(v.z, v.w));
    }
}

// ---------------------------------------------------------------------------
// Fused QKV GEMM, fp16 2-term (A split, B single), cp.async double-buffered,
// LDSM fragments.  Stage layout (words): Ah@0, Al@2560, Bh@5120; 7680 total.
// ---------------------------------------------------------------------------
#define BM 128
#define BN 128
#define KW 16
#define KP 20
#define GSTAGE 7680
#define NKIT (C2/KW)

#define GEMM_MMA_BLOCK()                                                      \
    do {                                                                      \
        _Pragma("unroll")                                                     \
        for (int p = 0; p < 2; p++)                                           \
            _Pragma("unroll")                                                 \
            for (int hb = 0; hb < 2; hb++)                                    \
                _Pragma("unroll")                                             \
                for (int mt = 0; mt < 4; mt++)                                \
                    mma_fp16(acc[mt][2 * p + hb], ah[mt], &bhf[p][2 * hb]);   \
        _Pragma("unroll")                                                     \
        for (int p = 0; p < 2; p++)                                           \
            _Pragma("unroll")                                                 \
            for (int hb = 0; hb < 2; hb++)                                    \
                _Pragma("unroll")                                             \
                for (int mt = 0; mt < 4; mt++)                                \
                    mma_fp16(acc[mt][2 * p + hb], al[mt], &bhf[p][2 * hb]);   \
    } while (0)

__global__ void __launch_bounds__(256, 2) qkv_gemm(const float* __restrict__ cosp,
                                                   const float* __restrict__ sinp) {
    extern __shared__ uint32_t sm[];
    const int tid = threadIdx.x, lane = tid & 31, warp = tid >> 5;
    const int warpM = warp >> 2, warpN = warp & 3;
    const int grp = lane >> 2, tg = lane & 3;
    const int m0 = blockIdx.y * BM;
    const int nsel = blockIdx.x >> 3;
    const int n0c = (blockIdx.x & 7) * BN;

    const uint32_t* W = (nsel == 0) ? g_wq : (nsel == 1) ? g_wk : g_wv;

    const int lrow = tid >> 2;
    const int lwq  = (tid & 3) << 2;
    const uint32_t sb = (uint32_t)__cvta_generic_to_shared(sm);
    const int lm = lane >> 3;
    const uint32_t aOffW = (uint32_t)((warpM * 64 + (lm & 1) * 8 + (lane & 7)) * KP
                                      + (lm >> 1) * 4);
    const uint32_t bOffW = (uint32_t)((warpN * 32 + (lm >> 1) * 8 + (lane & 7)) * KP
                                      + (lm & 1) * 4);

    float acc[4][4][4];
    #pragma unroll
    for (int mt = 0; mt < 4; mt++)
        #pragma unroll
        for (int nt = 0; nt < 4; nt++)
            #pragma unroll
            for (int i = 0; i < 4; i++) acc[mt][nt][i] = 0.f;

    #define QKV_ISSUE(stg, k0w) do {                                          \
        uint32_t base_ = sb + (stg) * (GSTAGE * 4);                           \
        size_t rA0_ = (size_t)(m0 + lrow) * C2 + (k0w) + lwq;                 \
        size_t rA1_ = (size_t)(m0 + lrow + 64) * C2 + (k0w) + lwq;            \
        size_t rB0_ = (size_t)(n0c + lrow) * C2 + (k0w) + lwq;                \
        size_t rB1_ = (size_t)(n0c + lrow + 64) * C2 + (k0w) + lwq;           \
        uint32_t dA0_ = base_ + (lrow * KP + lwq) * 4;                        \
        uint32_t dA1_ = base_ + ((lrow + 64) * KP + lwq) * 4;                 \
        cp16(dA0_, &g_xh[rA0_]);  cp16(dA1_, &g_xh[rA1_]);                    \
        cp16(dA0_ + 2560 * 4, &g_xl[rA0_]);                                   \
        cp16(dA1_ + 2560 * 4, &g_xl[rA1_]);                                   \
        uint32_t dB0_ = base_ + (5120 + lrow * KP + lwq) * 4;                 \
        uint32_t dB1_ = base_ + (5120 + (lrow + 64) * KP + lwq) * 4;          \
        cp16(dB0_, &W[rB0_]);  cp16(dB1_, &W[rB1_]);                          \
        CP_COMMIT();                                                          \
    } while (0)

    QKV_ISSUE(0, 0);

    for (int it = 0; it < NKIT; it++) {
        CP_WAIT0();
        __syncthreads();
        if (it + 1 < NKIT) QKV_ISSUE((it + 1) & 1, (it + 1) * KW);

        const uint32_t stg = sb + (it & 1) * (GSTAGE * 4);

        #pragma unroll
        for (int s8 = 0; s8 < KW; s8 += 8) {
            uint32_t ah[4][4], al[4][4];
            #pragma unroll
            for (int mt = 0; mt < 4; mt++) {
                ldsm_x4(ah[mt], stg + (mt * 16 * KP + s8 + aOffW) * 4);
                ldsm_x4(al[mt], stg + (2560 + mt * 16 * KP + s8 + aOffW) * 4);
            }
            uint32_t bhf[2][4];
            #pragma unroll
            for (int p = 0; p < 2; p++)
                ldsm_x4(bhf[p], stg + (5120 + p * 16 * KP + s8 + bOffW) * 4);
            GEMM_MMA_BLOCK();
        }
    }

    // epilogue (unchanged numerics: RoPE + bf16 splits for attention; V transposed)
    uint32_t* QKH = (nsel == 0) ? g_qh : g_kh;
    uint32_t* QKL = (nsel == 0) ? g_ql : g_kl;
    __nv_bfloat16* VTH = (__nv_bfloat16*)g_vth;
    __nv_bfloat16* VTL = (__nv_bfloat16*)g_vtl;
    #pragma unroll
    for (int mt = 0; mt < 4; mt++) {
        int rowA = m0 + warpM * 64 + mt * 16 + grp;
        int rowB = rowA + 8;
        #pragma unroll
        for (int nt = 0; nt < 4; nt++) {
            int c = n0c + warpN * 32 + nt * 8 + 2 * tg;
            float a0 = acc[mt][nt][0], a1 = acc[mt][nt][1];
            float a2 = acc[mt][nt][2], a3 = acc[mt][nt][3];
            if (nsel < 2) {
                int d = (c & 63) >> 1;
                int t0 = rowA & (T - 1), t1 = rowB & (T - 1);
                float c0 = cosp[t0 * 32 + d], s0 = sinp[t0 * 32 + d];
                float c1 = cosp[t1 * 32 + d], s1 = sinp[t1 * 32 + d];
                float o0 = a0 * c0 - a1 * s0, o1 = a0 * s0 + a1 * c0;
                float o2 = a2 * c1 - a3 * s1, o3 = a2 * s1 + a3 * c1;
                uint32_t hw, lw;
                splitpair(o0, o1, hw, lw);
                QKH[(size_t)rowA * C2 + (c >> 1)] = hw;
                QKL[(size_t)rowA * C2 + (c >> 1)] = lw;
                splitpair(o2, o3, hw, lw);
                QKH[(size_t)rowB * C2 + (c >> 1)] = hw;
                QKL[(size_t)rowB * C2 + (c >> 1)] = lw;
            } else {
                int bb = rowA >> 11;
                int hh = c >> 6, hd = c & 63;
                size_t base = ((size_t)(bb * H + hh) * HD + hd) * T;
                int tA = rowA & (T - 1), tB = rowB & (T - 1);
                float vals[4] = {a0, a1, a2, a3};
                size_t idxs[4] = {base + tA, base + T + tA,
                                  base + tB, base + T + tB};
                #pragma unroll
                for (int j = 0; j < 4; j++) {
                    __nv_bfloat16 hv, lv;
                    split1(vals[j], hv, lv);
                    VTH[idxs[j]] = hv;
                    VTL[idxs[j]] = lv;
                }
            }
        }
    }
}

// ---------------------------------------------------------------------------
// Output GEMM: out = att @ Wo^T, fp16 2-term.
// ---------------------------------------------------------------------------
__global__ void __launch_bounds__(256, 2) wo_gemm(float* __restrict__ out) {
    extern __shared__ uint32_t sm[];
    const int tid = threadIdx.x, lane = tid & 31, warp = tid >> 5;
    const int warpM = warp >> 2, warpN = warp & 3;
    const int grp = lane >> 2, tg = lane & 3;
    const int m0 = blockIdx.y * BM;
    const int n0 = blockIdx.x * BN;

    const int lrow = tid >> 2;
    const int lwq  = (tid & 3) << 2;
    const uint32_t sb = (uint32_t)__cvta_generic_to_shared(sm);
    const int lm = lane >> 3;
    const uint32_t aOffW = (uint32_t)((warpM * 64 + (lm & 1) * 8 + (lane & 7)) * KP
                                      + (lm >> 1) * 4);
    const uint32_t bOffW = (uint32_t)((warpN * 32 + (lm >> 1) * 8 + (lane & 7)) * KP
                                      + (lm & 1) * 4);

    float acc[4][4][4];
    #pragma unroll
    for (int mt = 0; mt < 4; mt++)
        #pragma unroll
        for (int nt = 0; nt < 4; nt++)
            #pragma unroll
            for (int i = 0; i < 4; i++) acc[mt][nt][i] = 0.f;

    #define WO_ISSUE(stg, k0w) do {                                           \
        uint32_t base_ = sb + (stg) * (GSTAGE * 4);                           \
        size_t rA0_ = (size_t)(m0 + lrow) * C2 + (k0w) + lwq;                 \
        size_t rA1_ = (size_t)(m0 + lrow + 64) * C2 + (k0w) + lwq;            \
        size_t rB0_ = (size_t)(n0 + lrow) * C2 + (k0w) + lwq;                 \
        size_t rB1_ = (size_t)(n0 + lrow + 64) * C2 + (k0w) + lwq;            \
        uint32_t dA0_ = base_ + (lrow * KP + lwq) * 4;                        \
        uint32_t dA1_ = base_ + ((lrow + 64) * KP + lwq) * 4;                 \
        cp16(dA0_, &g_ah[rA0_]);  cp16(dA1_, &g_ah[rA1_]);                    \
        cp16(dA0_ + 2560 * 4, &g_al[rA0_]);                                   \
        cp16(dA1_ + 2560 * 4, &g_al[rA1_]);                                   \
        uint32_t dB0_ = base_ + (5120 + lrow * KP + lwq) * 4;                 \
        uint32_t dB1_ = base_ + (5120 + (lrow + 64) * KP + lwq) * 4;          \
        cp16(dB0_, &g_wo[rB0_]);  cp16(dB1_, &g_wo[rB1_]);                    \
        CP_COMMIT();                                                          \
    } while (0)

    WO_ISSUE(0, 0);

    for (int it = 0; it < NKIT; it++) {
        CP_WAIT0();
        __syncthreads();
        if (it + 1 < NKIT) WO_ISSUE((it + 1) & 1, (it + 1) * KW);

        const uint32_t stg = sb + (it & 1) * (GSTAGE * 4);

        #pragma unroll
        for (int s8 = 0; s8 < KW; s8 += 8) {
            uint32_t ah[4][4], al[4][4];
            #pragma unroll
            for (int mt = 0; mt < 4; mt++) {
                ldsm_x4(ah[mt], stg + (mt * 16 * KP + s8 + aOffW) * 4);
                ldsm_x4(al[mt], stg + (2560 + mt * 16 * KP + s8 + aOffW) * 4);
            }
            uint32_t bhf[2][4];
            #pragma unroll
            for (int p = 0; p < 2; p++)
                ldsm_x4(bhf[p], stg + (5120 + p * 16 * KP + s8 + bOffW) * 4);
            GEMM_MMA_BLOCK();
        }
    }

    #pragma unroll
    for (int mt = 0; mt < 4; mt++) {
        int rowA = m0 + warpM * 64 + mt * 16 + grp;
        #pragma unroll
        for (int nt = 0; nt < 4; nt++) {
            int c = n0 + warpN * 32 + nt * 8 + 2 * tg;
            *(float2*)&out[(size_t)rowA * C + c] =
                make_float2(acc[mt][nt][0], acc[mt][nt][1]);
            *(float2*)&out[(size_t)(rowA + 8) * C + c] =
                make_float2(acc[mt][nt][2], acc[mt][nt][3]);
        }
    }
}

// ---------------------------------------------------------------------------
// Causal flash attention: bf16 3-term (validated), KB=64, LDSM, occ 3.
// Only change: output stores use fp16 splitpair (wo_gemm's A operand).
// ---------------------------------------------------------------------------
#define QB 64
#define KB 64
#define KSW 36
#define VSW 36
#define AST_KL 2304
#define AST_VH 4608
#define AST_VL 6912
#define ASTAGE 9216

__global__ void __launch_bounds__(128, 3) attn_kernel() {
    extern __shared__ uint32_t sm[];

    const int tid  = threadIdx.x;
    const int lane = tid & 31;
    const int warp = tid >> 5;
    const int grp  = lane >> 2;
    const int tg   = lane & 3;
    const int bh   = blockIdx.y;
    const int b    = bh >> 4, h = bh & 15;
    const int qx   = gridDim.x - 1 - (int)blockIdx.x;
    const int q0   = qx * QB;
    const int r0   = q0 + warp * 16;
    const uint32_t sb = (uint32_t)__cvta_generic_to_shared(sm);
    const size_t vbase = ((size_t)(b * H + h)) * HD * T2;
    const int lm = lane >> 3;
    const uint32_t kOffW = (uint32_t)(((lm >> 1) * 8 + (lane & 7)) * KSW
                                      + (lm & 1) * 4);
    const uint32_t vOffW = (uint32_t)(((lm >> 1) * 8 + (lane & 7)) * VSW
                                      + (lm & 1) * 4);

    uint32_t qfh[4][4], qfl[4][4];
    {
        const uint32_t* QHa = g_qh + ((size_t)(b * T + r0)) * C2 + h * 32;
        const uint32_t* QLa = g_ql + ((size_t)(b * T + r0)) * C2 + h * 32;
        #pragma unroll
        for (int ks = 0; ks < 4; ks++) {
            qfh[ks][0] = QHa[(size_t)grp * C2 + ks * 8 + tg];
            qfh[ks][1] = QHa[(size_t)(grp + 8) * C2 + ks * 8 + tg];
            qfh[ks][2] = QHa[(size_t)grp * C2 + ks * 8 + tg + 4];
            qfh[ks][3] = QHa[(size_t)(grp + 8) * C2 + ks * 8 + tg + 4];
            qfl[ks][0] = QLa[(size_t)grp * C2 + ks * 8 + tg];
            qfl[ks][1] = QLa[(size_t)(grp + 8) * C2 + ks * 8 + tg];
            qfl[ks][2] = QLa[(size_t)grp * C2 + ks * 8 + tg + 4];
            qfl[ks][3] = QLa[(size_t)(grp + 8) * C2 + ks * 8 + tg + 4];
        }
    }

    float out[8][4];
    #pragma unroll
    for (int i = 0; i < 8; i++)
        #pragma unroll
        for (int j = 0; j < 4; j++) out[i][j] = 0.f;
    float m0v = -1e30f, m1v = -1e30f, l0 = 0.f, l1 = 0.f;

    const int nIter = qx + 1;

    #define ATT_ISSUE(stg, k0) do {                                           \
        uint32_t base_ = sb + (stg) * (ASTAGE * 4);                           \
        _Pragma("unroll")                                                     \
        for (int i_ = 0; i_ < 4; i_++) {                                      \
            int idk_ = tid + i_ * 128;                                        \
            int krow_ = idk_ >> 3, kwq_ = (idk_ & 7) << 2;                    \
            size_t koff_ = ((size_t)(b * T + (k0) + krow_)) * C2 + h * 32 + kwq_; \
            cp16(base_ + (krow_ * KSW + kwq_) * 4, &g_kh[koff_]);             \
            cp16(base_ + (AST_KL + krow_ * KSW + kwq_) * 4, &g_kl[koff_]);    \
            size_t voff_ = vbase + (size_t)krow_ * T2 + ((k0) >> 1) + kwq_;   \
            cp16(base_ + (AST_VH + krow_ * VSW + kwq_) * 4, &g_vth[voff_]);   \
            cp16(base_ + (AST_VL + krow_ * VSW + kwq_) * 4, &g_vtl[voff_]);   \
        }                                                                     \
        CP_COMMIT();                                                          \
    } while (0)

    ATT_ISSUE(0, 0);

    for (int t = 0; t < nIter; t++) {
        const int k0 = t * KB;
        CP_WAIT0();
        __syncthreads();
        if (t + 1 < nIter) ATT_ISSUE((t + 1) & 1, (t + 1) * KB);

        if (k0 > r0 + 15) continue;

        const uint32_t stg = sb + (t & 1) * (ASTAGE * 4);

        float s[8][4];
        #pragma unroll
        for (int nt = 0; nt < 8; nt++)
            #pragma unroll
            for (int j = 0; j < 4; j++) s[nt][j] = 0.f;

        #pragma unroll
        for (int ks = 0; ks < 4; ks++) {
            uint32_t kh4[4][4], kl4[4][4];
            #pragma unroll
            for (int p = 0; p < 4; p++) {
                ldsm_x4(kh4[p], stg + (p * 16 * KSW + ks * 8 + kOffW) * 4);
                ldsm_x4(kl4[p], stg + (AST_KL * 4) + (p * 16 * KSW + ks * 8 + kOffW) * 4);
            }
            #pragma unroll
            for (int p = 0; p < 4; p++)
                #pragma unroll
                for (int hb = 0; hb < 2; hb++)
                    mma_bf16(s[2 * p + hb], qfh[ks], &kh4[p][2 * hb]);
            #pragma unroll
            for (int p = 0; p < 4; p++)
                #pragma unroll
                for (int hb = 0; hb < 2; hb++)
                    mma_bf16(s[2 * p + hb], qfl[ks], &kh4[p][2 * hb]);
            #pragma unroll
            for (int p = 0; p < 4; p++)
                #pragma unroll
                for (int hb = 0; hb < 2; hb++)
                    mma_bf16(s[2 * p + hb], qfh[ks], &kl4[p][2 * hb]);
        }

        const int row0 = r0 + grp, row1 = r0 + grp + 8;
        if (k0 + KB - 1 <= r0) {
            #pragma unroll
            for (int nt = 0; nt < 8; nt++)
                #pragma unroll
                for (int j = 0; j < 4; j++) s[nt][j] *= 0.125f;
        } else {
            #pragma unroll
            for (int nt = 0; nt < 8; nt++) {
                int col = k0 + nt * 8 + 2 * tg;
                s[nt][0] = (col     <= row0) ? s[nt][0] * 0.125f : -1e30f;
                s[nt][1] = (col + 1 <= row0) ? s[nt][1] * 0.125f : -1e30f;
                s[nt][2] = (col     <= row1) ? s[nt][2] * 0.125f : -1e30f;
                s[nt][3] = (col + 1 <= row1) ? s[nt][3] * 0.125f : -1e30f;
            }
        }

        float mx0 = s[0][0], mx1 = s[0][2];
        #pragma unroll
        for (int nt = 0; nt < 8; nt++) {
            mx0 = fmaxf(mx0, fmaxf(s[nt][0], s[nt][1]));
            mx1 = fmaxf(mx1, fmaxf(s[nt][2], s[nt][3]));
        }
        mx0 = fmaxf(mx0, __shfl_xor_sync(0xffffffffu, mx0, 1));
        mx0 = fmaxf(mx0, __shfl_xor_sync(0xffffffffu, mx0, 2));
        mx1 = fmaxf(mx1, __shfl_xor_sync(0xffffffffu, mx1, 1));
        mx1 = fmaxf(mx1, __shfl_xor_sync(0xffffffffu, mx1, 2));
        float nm0 = fmaxf(m0v, mx0), nm1 = fmaxf(m1v, mx1);
        float c0 = __expf(m0v - nm0), c1 = __expf(m1v - nm1);

        float sum0 = 0.f, sum1 = 0.f;
        #pragma unroll
        for (int nt = 0; nt < 8; nt++) {
            s[nt][0] = __expf(s[nt][0] - nm0);
            s[nt][1] = __expf(s[nt][1] - nm0);
            s[nt][2] = __expf(s[nt][2] - nm1);
            s[nt][3] = __expf(s[nt][3] - nm1);
            sum0 += s[nt][0] + s[nt][1];
            sum1 += s[nt][2] + s[nt][3];
        }
        sum0 += __shfl_xor_sync(0xffffffffu, sum0, 1);
        sum0 += __shfl_xor_sync(0xffffffffu, sum0, 2);
        sum1 += __shfl_xor_sync(0xffffffffu, sum1, 1);
        sum1 += __shfl_xor_sync(0xffffffffu, sum1, 2);
        l0 = l0 * c0 + sum0;
        l1 = l1 * c1 + sum1;
        m0v = nm0; m1v = nm1;

        #pragma unroll
        for (int i = 0; i < 8; i++) {
            out[i][0] *= c0; out[i][1] *= c0;
            out[i][2] *= c1; out[i][3] *= c1;
        }

        #pragma unroll
        for (int ks = 0; ks < 4; ks++) {
            uint32_t ph[4], pl[4];
            splitpair(s[2 * ks][0],     s[2 * ks][1],     ph[0], pl[0]);
            splitpair(s[2 * ks][2],     s[2 * ks][3],     ph[1], pl[1]);
            splitpair(s[2 * ks + 1][0], s[2 * ks + 1][1], ph[2], pl[2]);
            splitpair(s[2 * ks + 1][2], s[2 * ks + 1][3], ph[3], pl[3]);
            uint32_t vh4[4][4], vl4[4][4];
            #pragma unroll
            for (int p = 0; p < 4; p++) {
                ldsm_x4(vh4[p], stg + (AST_VH * 4) + (p * 16 * VSW + ks * 8 + vOffW) * 4);
                ldsm_x4(vl4[p], stg + (AST_VL * 4) + (p * 16 * VSW + ks * 8 + vOffW) * 4);
            }
            #pragma unroll
            for (int p = 0; p < 4; p++)
                #pragma unroll
                for (int hb = 0; hb < 2; hb++)
                    mma_bf16(out[2 * p + hb], ph, &vh4[p][2 * hb]);
            #pragma unroll
            for (int p = 0; p < 4; p++)
                #pragma unroll
                for (int hb = 0; hb < 2; hb++)
                    mma_bf16(out[2 * p + hb], pl, &vh4[p][2 * hb]);
            #pragma unroll
            for (int p = 0; p < 4; p++)
                #pragma unroll
                for (int hb = 0; hb < 2; hb++)
                    mma_bf16(out[2 * p + hb], ph, &vl4[p][2 * hb]);
        }
    }

    // normalize + fp16 splitpair + packed store (wo_gemm consumes fp16)
    float inv0 = 1.f / l0, inv1 = 1.f / l1;
    size_t rA = ((size_t)(b * T + r0 + grp)) * C2 + h * 32;
    size_t rB = ((size_t)(b * T + r0 + grp + 8)) * C2 + h * 32;
    #pragma unroll
    for (int ntv = 0; ntv < 8; ntv++) {
        int cw = ntv * 4 + tg;
        uint32_t hw, lw;
        splitpair_h(out[ntv][0] * inv0, out[ntv][1] * inv0, hw, lw);
        g_ah[rA + cw] = hw;
        g_al[rA + cw] = lw;
        splitpair_h(out[ntv][2] * inv1, out[ntv][3] * inv1, hw, lw);
        g_ah[rB + cw] = hw;
        g_al[rB + cw] = lw;
    }
}

// ---------------------------------------------------------------------------
extern "C" void kernel_launch(void* const* d_in, const int* in_sizes, int n_in,
                              void* d_out, int out_size) {
    const float* x    = (const float*)d_in[0];
    const float* Wq   = (const float*)d_in[1];
    const float* Wk   = (const float*)d_in[2];
    const float* Wv   = (const float*)d_in[3];
    const float* Wo   = (const float*)d_in[4];
    const float* cosp = (const float*)d_in[5];
    const float* sinp = (const float*)d_in[6];
    float* out = (float*)d_out;

    static bool attr_done = false;
    if (!attr_done) {
        cudaFuncSetAttribute(qkv_gemm,
            cudaFuncAttributeMaxDynamicSharedMemorySize, 2 * GSTAGE * 4);
        cudaFuncSetAttribute(wo_gemm,
            cudaFuncAttributeMaxDynamicSharedMemorySize, 2 * GSTAGE * 4);
        cudaFuncSetAttribute(attn_kernel,
            cudaFuncAttributeMaxDynamicSharedMemorySize, 2 * ASTAGE * 4);
        attr_done = true;
    }

    int nx4 = M_TOT * C / 4;
    int nw4 = C * C / 4;
    split5_kernel<<<dim3(nx4 / 256, 5), 256>>>(
        (const float4*)x, (const float4*)Wq, (const float4*)Wk,
        (const float4*)Wv, (const float4*)Wo, nx4, nw4);

    qkv_gemm<<<dim3(24, M_TOT / BM), 256, 2 * GSTAGE * 4>>>(cosp, sinp);

    attn_kernel<<<dim3(T / QB, B * H), 128, 2 * ASTAGE * 4>>>();

    wo_gemm<<<dim3(C / BN, M_TOT / BM), 256, 2 * GSTAGE * 4>>>(out);
}